// round 8
// baseline (speedup 1.0000x reference)
#include <cuda_runtime.h>
#include <cstddef>
#include <cstdint>

#define NROWS 16384
#define INDIM 768
#define CDIM  256
#define KCODES 4096

// ---- device scratch (static: allowed; no runtime allocation) ----
__device__ float g_zqsum[NROWS * CDIM];      // running zq sum -> decoder input
__device__ float g_esq[4][KCODES];           // ||E_k||^2 per codebook
__device__ float g_ze2[NROWS];               // ||ze||^2 for current stage
__device__ float g_bestv4[4][NROWS];         // per-quarter best distance
__device__ int   g_besti4[4][NROWS];         // per-quarter best index
__device__ float g_ET[4][CDIM * KCODES];     // codebooks transposed [c][code]

// ---- packed f32x2 helpers: each lane rounds .rn independently, so each
// output keeps its single ascending-k fma chain -> bit-exact vs scalar ----
__device__ __forceinline__ void fma2(unsigned long long& d,
                                     unsigned long long a,
                                     unsigned long long b)
{
    asm("fma.rn.f32x2 %0, %1, %2, %0;" : "+l"(d) : "l"(a), "l"(b));
}
__device__ __forceinline__ unsigned long long dup2(float x)
{
    unsigned long long r;
    asm("mov.b64 %0, {%1, %1};" : "=l"(r) : "f"(x));
    return r;
}
__device__ __forceinline__ float2 unpk2(unsigned long long v)
{
    float2 r;
    asm("mov.b64 {%0, %1}, %2;" : "=f"(r.x), "=f"(r.y) : "l"(v));
    return r;
}
__device__ __forceinline__ void cp_async16(uint32_t dst_smem, const void* src)
{
    asm volatile("cp.async.cg.shared.global [%0], [%1], 16;"
                 :: "r"(dst_smem), "l"(src) : "memory");
}

// ============================================================================
// fp32 SGEMM with bias via packed f32x2: C = A @ B + bias.
// 128x128 tile, 8x8 per thread (4 f32x2 column-pairs).
// ============================================================================
__global__ __launch_bounds__(256) void sgemm_bias_kernel(
    const float* __restrict__ A, const float* __restrict__ B,
    const float* __restrict__ bias, float* __restrict__ C,
    int M, int Kd, int Nn)
{
    __shared__ __align__(16) float As[32][132];  // [kk][mm]
    __shared__ __align__(16) float Bs[32][132];  // [kk][nn]

    const int tid = threadIdx.x;
    const int tx = tid & 15;
    const int ty = tid >> 4;
    const int m0 = blockIdx.y * 128;
    const int n0 = blockIdx.x * 128;

    unsigned long long acc[8][4];
#pragma unroll
    for (int i = 0; i < 8; i++)
#pragma unroll
        for (int j = 0; j < 4; j++) acc[i][j] = 0ull;

    for (int k0 = 0; k0 < Kd; k0 += 32) {
#pragma unroll
        for (int i = 0; i < 16; i++) {
            int idx = tid + i * 256;
            int mm = idx >> 5, kk = idx & 31;
            As[kk][mm] = A[(size_t)(m0 + mm) * Kd + (k0 + kk)];
        }
#pragma unroll
        for (int i = 0; i < 16; i++) {
            int idx = tid + i * 256;
            int kk = idx >> 7, nn = idx & 127;
            Bs[kk][nn] = B[(size_t)(k0 + kk) * Nn + (n0 + nn)];
        }
        __syncthreads();

#pragma unroll
        for (int kk = 0; kk < 32; kk++) {
            float4 a0 = *(const float4*)&As[kk][ty * 4];
            float4 a1 = *(const float4*)&As[kk][64 + ty * 4];
            unsigned long long aa[8] = {dup2(a0.x), dup2(a0.y), dup2(a0.z), dup2(a0.w),
                                        dup2(a1.x), dup2(a1.y), dup2(a1.z), dup2(a1.w)};
            ulonglong2 b0 = *(const ulonglong2*)&Bs[kk][tx * 4];
            ulonglong2 b1 = *(const ulonglong2*)&Bs[kk][64 + tx * 4];
            unsigned long long bb[4] = {b0.x, b0.y, b1.x, b1.y};
#pragma unroll
            for (int i = 0; i < 8; i++)
#pragma unroll
                for (int j = 0; j < 4; j++)
                    fma2(acc[i][j], aa[i], bb[j]);
        }
        __syncthreads();
    }

#pragma unroll
    for (int i = 0; i < 8; i++) {
        int row = m0 + ((i < 4) ? (ty * 4 + i) : (64 + ty * 4 + (i - 4)));
#pragma unroll
        for (int jh = 0; jh < 2; jh++) {
            int col = n0 + (jh ? (64 + tx * 4) : (tx * 4));
            float2 p0 = unpk2(acc[i][jh * 2 + 0]);
            float2 p1 = unpk2(acc[i][jh * 2 + 1]);
            float4 v;
            v.x = __fadd_rn(p0.x, bias[col + 0]);
            v.y = __fadd_rn(p0.y, bias[col + 1]);
            v.z = __fadd_rn(p1.x, bias[col + 2]);
            v.w = __fadd_rn(p1.y, bias[col + 3]);
            *(float4*)&C[(size_t)row * Nn + col] = v;
        }
    }
}

// ============================================================================
// Tiled transpose of all 4 codebooks: E[code][c] -> g_ET[stage][c][code].
// ============================================================================
__global__ void transpose4_kernel(const float* __restrict__ E0,
                                  const float* __restrict__ E1,
                                  const float* __restrict__ E2,
                                  const float* __restrict__ E3)
{
    __shared__ float tile[32][33];
    int stage = blockIdx.z;
    const float* E = (stage == 0) ? E0 : (stage == 1) ? E1 : (stage == 2) ? E2 : E3;
    int code0 = blockIdx.x * 32;
    int c0 = blockIdx.y * 32;
    int txx = threadIdx.x, tyy = threadIdx.y;
#pragma unroll
    for (int r = 0; r < 4; r++) {
        int row = tyy + r * 8;
        tile[row][txx] = E[(size_t)(code0 + row) * CDIM + (c0 + txx)];
    }
    __syncthreads();
    float* ET = g_ET[stage];
#pragma unroll
    for (int r = 0; r < 4; r++) {
        int row = tyy + r * 8;
        ET[(size_t)(c0 + row) * KCODES + (code0 + txx)] = tile[txx][row];
    }
}

// ============================================================================
// ||E_k||^2, coalesced: stage = blockIdx.y; 32 codes per block staged through
// smem, then 32 threads run the exact sequential mul+add chain (XLA order).
// ============================================================================
__global__ __launch_bounds__(256) void esq4_kernel(
    const float* __restrict__ E0, const float* __restrict__ E1,
    const float* __restrict__ E2, const float* __restrict__ E3)
{
    __shared__ float s[32][257];
    int stage = blockIdx.y;
    const float* E = (stage == 0) ? E0 : (stage == 1) ? E1 : (stage == 2) ? E2 : E3;
    int row0 = blockIdx.x * 32;
    int tid = threadIdx.x;
#pragma unroll
    for (int i = 0; i < 32; i++) {
        int idx = tid + i * 256;           // 0..8191
        int r = idx >> 8, c = idx & 255;
        s[r][c] = E[(size_t)(row0 + r) * CDIM + c];
    }
    __syncthreads();
    if (tid < 32) {
        float acc = 0.f;
#pragma unroll 8
        for (int c = 0; c < CDIM; c++) {
            float v = s[tid][c];
            acc = __fadd_rn(acc, __fmul_rn(v, v));
        }
        g_esq[stage][row0 + tid] = acc;
    }
}

// ============================================================================
// ||ze||^2, coalesced (stage 0 only; later stages fused into gather).
// ============================================================================
__global__ __launch_bounds__(256) void rownorm_kernel(const float* __restrict__ ze)
{
    __shared__ float s[32][257];
    int row0 = blockIdx.x * 32;
    int tid = threadIdx.x;
#pragma unroll
    for (int i = 0; i < 32; i++) {
        int idx = tid + i * 256;
        int r = idx >> 8, c = idx & 255;
        s[r][c] = ze[(size_t)(row0 + r) * CDIM + c];
    }
    __syncthreads();
    if (tid < 32) {
        float acc = 0.f;
#pragma unroll 8
        for (int c = 0; c < CDIM; c++) {
            float v = s[tid][c];
            acc = __fadd_rn(acc, __fmul_rn(v, v));
        }
        g_ze2[row0 + tid] = acc;
    }
}

// ============================================================================
// Fused score-GEMM + argmin over a QUARTER of the codebook (1024 codes).
// grid (128 row-blocks, 4 quarters) = 512 CTAs -> fills all 152 SMs via
// work-stealing. BM=128 x BN=256/chunk, BK=32, 512 threads, 8x8/thread.
// Persistent ze tile; double-buffered cp.async E tiles from g_ET.
// d_k = fl( fl( Z - fl(2*s_k) ) + esq_k ); single fma chain per score.
// Dynamic smem: As 256x132 | Bs 2 x 32x264 = 202,752 B.
// ============================================================================
#define ASTRIDE 132
#define BSTRIDE 264
#define VQ_SMEM ((256 * ASTRIDE + 2 * 32 * BSTRIDE) * 4)

__global__ __launch_bounds__(512, 1) void vq_argmin_kernel(
    const float* __restrict__ ze,   // NROWS x CDIM
    int stage)
{
    extern __shared__ __align__(16) float sm[];
    float* As = sm;                         // [256 c][ASTRIDE]  persistent
    float* Bs = sm + 256 * ASTRIDE;         // [2][32 kk][BSTRIDE]

    const int tid = threadIdx.x;
    const int tx = tid & 31;                // code group 0..31
    const int ty = tid >> 5;                // row group  0..15
    const int m0 = blockIdx.x * 128;
    const int q = blockIdx.y;               // quarter 0..3
    const int code0 = q * 1024;
    const float* __restrict__ esq = g_esq[stage];
    const float* __restrict__ ET = g_ET[stage];

    const uint32_t bs_u32 = (uint32_t)__cvta_generic_to_shared(Bs);

    // ---- kick off async copy of chunk 0 (cb=code0, c0=0) ----
#pragma unroll
    for (int i = 0; i < 4; i++) {
        int idx = tid + i * 512;            // 0..2047 float4 units
        int kk = idx >> 6, c4 = idx & 63;
        cp_async16(bs_u32 + (uint32_t)(kk * BSTRIDE + c4 * 4) * 4,
                   ET + (size_t)kk * KCODES + code0 + c4 * 4);
    }
    asm volatile("cp.async.commit_group;" ::: "memory");

    // ---- one-time fill of the ze tile (128 rows x 256 c), coalesced ----
#pragma unroll 8
    for (int i = 0; i < 64; i++) {
        int idx = tid + i * 512;
        int c = idx & 255, mm = idx >> 8;
        As[c * ASTRIDE + mm] = ze[(size_t)(m0 + mm) * CDIM + c];
    }

    float zrow[8];
#pragma unroll
    for (int i = 0; i < 8; i++) {
        int row = (i < 4) ? (ty * 4 + i) : (64 + ty * 4 + (i - 4));
        zrow[i] = g_ze2[m0 + row];
    }

    float bestv[8];
    int   besti[8];
#pragma unroll
    for (int i = 0; i < 8; i++) { bestv[i] = 3.4e38f; besti[i] = 0; }

    unsigned long long acc[8][4];

    // 32 chunks: t -> cb = code0 + (t>>3)*256, c0 = (t&7)*32
    for (int t = 0; t < 32; t++) {
        asm volatile("cp.async.wait_group 0;" ::: "memory");
        __syncthreads();   // chunk t resident; everyone done with other buffer

        // launch async copy of chunk t+1 into the other buffer
        if (t < 31) {
            const int t1 = t + 1;
            const int cb1 = code0 + (t1 >> 3) * 256;
            const int c01 = (t1 & 7) * 32;
            const uint32_t dstb = bs_u32 +
                (uint32_t)((t1 & 1) * 32 * BSTRIDE) * 4;
#pragma unroll
            for (int i = 0; i < 4; i++) {
                int idx = tid + i * 512;
                int kk = idx >> 6, c4 = idx & 63;
                cp_async16(dstb + (uint32_t)(kk * BSTRIDE + c4 * 4) * 4,
                           ET + (size_t)(c01 + kk) * KCODES + cb1 + c4 * 4);
            }
            asm volatile("cp.async.commit_group;" ::: "memory");
        }

        const int cb = code0 + (t >> 3) * 256;
        const int c0 = (t & 7) * 32;

        if ((t & 7) == 0) {
#pragma unroll
            for (int i = 0; i < 8; i++)
#pragma unroll
                for (int j = 0; j < 4; j++) acc[i][j] = 0ull;
        }

        const float* Bp = Bs + (t & 1) * (32 * BSTRIDE);
#pragma unroll
        for (int kk = 0; kk < 32; kk++) {
            const float* ar = As + (c0 + kk) * ASTRIDE;
            const float* br = Bp + kk * BSTRIDE;
            float4 a0 = *(const float4*)&ar[ty * 4];          // broadcast
            float4 a1 = *(const float4*)&ar[64 + ty * 4];     // broadcast
            unsigned long long aa[8] = {dup2(a0.x), dup2(a0.y), dup2(a0.z), dup2(a0.w),
                                        dup2(a1.x), dup2(a1.y), dup2(a1.z), dup2(a1.w)};
            ulonglong2 b0 = *(const ulonglong2*)&br[tx * 4];
            ulonglong2 b1 = *(const ulonglong2*)&br[128 + tx * 4];
            unsigned long long bb[4] = {b0.x, b0.y, b1.x, b1.y};
#pragma unroll
            for (int i = 0; i < 8; i++)
#pragma unroll
                for (int j = 0; j < 4; j++)
                    fma2(acc[i][j], aa[i], bb[j]);
        }

        // end of a cb group: argmin update  d = fl( fl(Z - fl(2*s)) + esq )
        if ((t & 7) == 7) {
#pragma unroll
            for (int half = 0; half < 2; half++) {
#pragma unroll
                for (int h = 0; h < 2; h++) {
                    int j2 = half * 2 + h;
                    int col = cb + half * 128 + tx * 4 + h * 2;
                    float eq0 = esq[col];
                    float eq1 = esq[col + 1];
#pragma unroll
                    for (int i = 0; i < 8; i++) {
                        float2 pv = unpk2(acc[i][j2]);
                        float t0 = __fmul_rn(2.0f, pv.x);
                        float v0 = __fadd_rn(__fadd_rn(zrow[i], -t0), eq0);
                        if (v0 < bestv[i]) { bestv[i] = v0; besti[i] = col; }
                        float t1v = __fmul_rn(2.0f, pv.y);
                        float v1 = __fadd_rn(__fadd_rn(zrow[i], -t1v), eq1);
                        if (v1 < bestv[i]) { bestv[i] = v1; besti[i] = col + 1; }
                    }
                }
            }
        }
    }

    // cross-thread reduction over the 32 tx lanes sharing each row
    __syncthreads();
    float* rv = sm;                    // 128*32 floats
    int*   ri = (int*)(sm + 4096);     // 128*32 ints
#pragma unroll
    for (int i = 0; i < 8; i++) {
        int row = (i < 4) ? (ty * 4 + i) : (64 + ty * 4 + (i - 4));
        rv[row * 32 + tx] = bestv[i];
        ri[row * 32 + tx] = besti[i];
    }
    __syncthreads();
    if (tid < 128) {
        float bv = rv[tid * 32];
        int   bi = ri[tid * 32];
#pragma unroll
        for (int tt = 1; tt < 32; tt++) {
            float v = rv[tid * 32 + tt];
            int  ix = ri[tid * 32 + tt];
            if (v < bv || (v == bv && ix < bi)) { bv = v; bi = ix; }
        }
        g_bestv4[q][m0 + tid] = bv;
        g_besti4[q][m0 + tid] = bi;
    }
}

// ============================================================================
// Gather: merge 4 quarter-argmins (strict < keeps lowest quarter/first
// occurrence); zq = E[nn]; residual; nn as float; accumulate zq_sum; stage 3
// forms straight-through decoder input. Stages 0-2 also compute the NEXT
// stage's ||ze_next||^2 with the exact sequential XLA chain.
// ============================================================================
__global__ void gather_kernel(const float* __restrict__ ze,
                              const float* __restrict__ E,
                              float* __restrict__ zq_out,
                              float* __restrict__ ze_next,   // null on stage 3
                              float* __restrict__ nn_f,
                              const float* __restrict__ ze1, // stage 3 only
                              int stage)
{
    __shared__ float buf[CDIM];
    int row = blockIdx.x;
    int c = threadIdx.x;

    // merge quarters (redundantly per thread; L2/L1 broadcast)
    float bv = g_bestv4[0][row];
    int   bi = g_besti4[0][row];
#pragma unroll
    for (int h = 1; h < 4; h++) {
        float v = g_bestv4[h][row];
        int  ix = g_besti4[h][row];
        if (v < bv) { bv = v; bi = ix; }
    }
    int idx = bi;

    float q = E[(size_t)idx * CDIM + c];
    size_t o = (size_t)row * CDIM + c;
    zq_out[o] = q;
    if (ze_next) {
        float zn = __fadd_rn(ze[o], -q);
        ze_next[o] = zn;
        buf[c] = zn;
    }
    float s = (stage == 0) ? q : __fadd_rn(g_zqsum[o], q);
    if (stage == 3) {
        float z1 = ze1[o];
        s = __fadd_rn(z1, __fadd_rn(s, -z1));   // ze1 + (zq_sum - ze1)
    }
    g_zqsum[o] = s;
    if (c == 0) nn_f[row] = (float)idx;

    if (ze_next) {
        __syncthreads();
        if (c == 0) {
            float acc = 0.f;
#pragma unroll 8
            for (int i = 0; i < CDIM; i++)
                acc = __fadd_rn(acc, __fmul_rn(buf[i], buf[i]));
            g_ze2[row] = acc;
        }
    }
}

// ============================================================================
// kernel_launch
// Output layout (float32): x_hat [N,768] | ze_1..4 [N,256] | zq_1..4 [N,256]
//                          | nn_1..4 [N]
// ============================================================================
extern "C" void kernel_launch(void* const* d_in, const int* in_sizes, int n_in,
                              void* d_out, int out_size)
{
    const float* x     = (const float*)d_in[0];
    const float* W_enc = (const float*)d_in[1];
    const float* b_enc = (const float*)d_in[2];
    const float* E[4]  = {(const float*)d_in[3], (const float*)d_in[4],
                          (const float*)d_in[5], (const float*)d_in[6]};
    const float* W_dec = (const float*)d_in[7];
    const float* b_dec = (const float*)d_in[8];

    float* out = (float*)d_out;

    const size_t NC      = (size_t)NROWS * CDIM;
    const size_t OFF_ZE  = (size_t)NROWS * INDIM;
    const size_t OFF_ZQ  = OFF_ZE + 4 * NC;
    const size_t OFF_NN  = OFF_ZQ + 4 * NC;

    float* xhat = out;
    const float* ze1 = out + OFF_ZE;

    void* zqsum_ptr = nullptr;
    cudaGetSymbolAddress(&zqsum_ptr, g_zqsum);

    cudaFuncSetAttribute(vq_argmin_kernel,
                         cudaFuncAttributeMaxDynamicSharedMemorySize, VQ_SMEM);

    // codebook preprocessing: norms + transposes (one-time)
    esq4_kernel<<<dim3(KCODES / 32, 4), 256>>>(E[0], E[1], E[2], E[3]);
    transpose4_kernel<<<dim3(KCODES / 32, CDIM / 32, 4), dim3(32, 8)>>>(
        E[0], E[1], E[2], E[3]);

    // encoder: ze_1 = x @ W_enc + b_enc
    sgemm_bias_kernel<<<dim3(CDIM / 128, NROWS / 128), 256>>>(
        x, W_enc, b_enc, out + OFF_ZE, NROWS, INDIM, CDIM);

    // ||ze_1||^2 (later stages' norms are fused into gather)
    rownorm_kernel<<<NROWS / 32, 256>>>(out + OFF_ZE);

    // 4 sequential VQ stages
    for (int s = 0; s < 4; s++) {
        const float* zes = out + OFF_ZE + (size_t)s * NC;
        vq_argmin_kernel<<<dim3(NROWS / 128, 4), 512, VQ_SMEM>>>(zes, s);
        float* zenext = (s < 3) ? (out + OFF_ZE + (size_t)(s + 1) * NC) : nullptr;
        gather_kernel<<<NROWS, 256>>>(zes, E[s],
                                      out + OFF_ZQ + (size_t)s * NC,
                                      zenext,
                                      out + OFF_NN + (size_t)s * NROWS,
                                      ze1, s);
    }

    // decoder: x_hat = decoder_input @ W_dec + b_dec
    sgemm_bias_kernel<<<dim3(INDIM / 128, NROWS / 128), 256>>>(
        (const float*)zqsum_ptr, W_dec, b_dec, xhat, NROWS, CDIM, INDIM);
}

// round 9
// speedup vs baseline: 1.0997x; 1.0997x over previous
#include <cuda_runtime.h>
#include <cstddef>
#include <cstdint>

#define NROWS 16384
#define INDIM 768
#define CDIM  256
#define KCODES 4096
#define NUNITS 2048      // 128 row-blocks x 16 code-groups (256 codes each)
#define VQ_GRID 148

// ---- device scratch (static: allowed; no runtime allocation) ----
__device__ float g_zqsum[NROWS * CDIM];      // running zq sum -> decoder input
__device__ float g_esq[4][KCODES];           // ||E_k||^2 per codebook
__device__ float g_ze2[NROWS];               // ||ze||^2 for current stage
__device__ float g_bestv16[16][NROWS];       // per-code-group best distance
__device__ int   g_besti16[16][NROWS];       // per-code-group best index
__device__ float g_ET[4][CDIM * KCODES];     // codebooks transposed [c][code]

// ---- packed f32x2 helpers: each lane rounds .rn independently, so each
// output keeps its single ascending-k fma chain -> bit-exact vs scalar ----
__device__ __forceinline__ void fma2(unsigned long long& d,
                                     unsigned long long a,
                                     unsigned long long b)
{
    asm("fma.rn.f32x2 %0, %1, %2, %0;" : "+l"(d) : "l"(a), "l"(b));
}
__device__ __forceinline__ unsigned long long dup2(float x)
{
    unsigned long long r;
    asm("mov.b64 %0, {%1, %1};" : "=l"(r) : "f"(x));
    return r;
}
__device__ __forceinline__ float2 unpk2(unsigned long long v)
{
    float2 r;
    asm("mov.b64 {%0, %1}, %2;" : "=f"(r.x), "=f"(r.y) : "l"(v));
    return r;
}
__device__ __forceinline__ void cp_async16(uint32_t dst_smem, const void* src)
{
    asm volatile("cp.async.cg.shared.global [%0], [%1], 16;"
                 :: "r"(dst_smem), "l"(src) : "memory");
}

// ============================================================================
// fp32 SGEMM with bias via packed f32x2: C = A @ B + bias.
// 128x128 tile, 8x8 per thread (4 f32x2 column-pairs).
// ============================================================================
__global__ __launch_bounds__(256) void sgemm_bias_kernel(
    const float* __restrict__ A, const float* __restrict__ B,
    const float* __restrict__ bias, float* __restrict__ C,
    int M, int Kd, int Nn)
{
    __shared__ __align__(16) float As[32][132];  // [kk][mm]
    __shared__ __align__(16) float Bs[32][132];  // [kk][nn]

    const int tid = threadIdx.x;
    const int tx = tid & 15;
    const int ty = tid >> 4;
    const int m0 = blockIdx.y * 128;
    const int n0 = blockIdx.x * 128;

    unsigned long long acc[8][4];
#pragma unroll
    for (int i = 0; i < 8; i++)
#pragma unroll
        for (int j = 0; j < 4; j++) acc[i][j] = 0ull;

    for (int k0 = 0; k0 < Kd; k0 += 32) {
#pragma unroll
        for (int i = 0; i < 16; i++) {
            int idx = tid + i * 256;
            int mm = idx >> 5, kk = idx & 31;
            As[kk][mm] = A[(size_t)(m0 + mm) * Kd + (k0 + kk)];
        }
#pragma unroll
        for (int i = 0; i < 16; i++) {
            int idx = tid + i * 256;
            int kk = idx >> 7, nn = idx & 127;
            Bs[kk][nn] = B[(size_t)(k0 + kk) * Nn + (n0 + nn)];
        }
        __syncthreads();

#pragma unroll
        for (int kk = 0; kk < 32; kk++) {
            float4 a0 = *(const float4*)&As[kk][ty * 4];
            float4 a1 = *(const float4*)&As[kk][64 + ty * 4];
            unsigned long long aa[8] = {dup2(a0.x), dup2(a0.y), dup2(a0.z), dup2(a0.w),
                                        dup2(a1.x), dup2(a1.y), dup2(a1.z), dup2(a1.w)};
            ulonglong2 b0 = *(const ulonglong2*)&Bs[kk][tx * 4];
            ulonglong2 b1 = *(const ulonglong2*)&Bs[kk][64 + tx * 4];
            unsigned long long bb[4] = {b0.x, b0.y, b1.x, b1.y};
#pragma unroll
            for (int i = 0; i < 8; i++)
#pragma unroll
                for (int j = 0; j < 4; j++)
                    fma2(acc[i][j], aa[i], bb[j]);
        }
        __syncthreads();
    }

#pragma unroll
    for (int i = 0; i < 8; i++) {
        int row = m0 + ((i < 4) ? (ty * 4 + i) : (64 + ty * 4 + (i - 4)));
#pragma unroll
        for (int jh = 0; jh < 2; jh++) {
            int col = n0 + (jh ? (64 + tx * 4) : (tx * 4));
            float2 p0 = unpk2(acc[i][jh * 2 + 0]);
            float2 p1 = unpk2(acc[i][jh * 2 + 1]);
            float4 v;
            v.x = __fadd_rn(p0.x, bias[col + 0]);
            v.y = __fadd_rn(p0.y, bias[col + 1]);
            v.z = __fadd_rn(p1.x, bias[col + 2]);
            v.w = __fadd_rn(p1.y, bias[col + 3]);
            *(float4*)&C[(size_t)row * Nn + col] = v;
        }
    }
}

// ============================================================================
// Tiled transpose of all 4 codebooks: E[code][c] -> g_ET[stage][c][code].
// ============================================================================
__global__ void transpose4_kernel(const float* __restrict__ E0,
                                  const float* __restrict__ E1,
                                  const float* __restrict__ E2,
                                  const float* __restrict__ E3)
{
    __shared__ float tile[32][33];
    int stage = blockIdx.z;
    const float* E = (stage == 0) ? E0 : (stage == 1) ? E1 : (stage == 2) ? E2 : E3;
    int code0 = blockIdx.x * 32;
    int c0 = blockIdx.y * 32;
    int txx = threadIdx.x, tyy = threadIdx.y;
#pragma unroll
    for (int r = 0; r < 4; r++) {
        int row = tyy + r * 8;
        tile[row][txx] = E[(size_t)(code0 + row) * CDIM + (c0 + txx)];
    }
    __syncthreads();
    float* ET = g_ET[stage];
#pragma unroll
    for (int r = 0; r < 4; r++) {
        int row = tyy + r * 8;
        ET[(size_t)(c0 + row) * KCODES + (code0 + txx)] = tile[txx][row];
    }
}

// ============================================================================
// ||E_k||^2, coalesced smem-staged, exact sequential mul+add chain.
// ============================================================================
__global__ __launch_bounds__(256) void esq4_kernel(
    const float* __restrict__ E0, const float* __restrict__ E1,
    const float* __restrict__ E2, const float* __restrict__ E3)
{
    __shared__ float s[32][257];
    int stage = blockIdx.y;
    const float* E = (stage == 0) ? E0 : (stage == 1) ? E1 : (stage == 2) ? E2 : E3;
    int row0 = blockIdx.x * 32;
    int tid = threadIdx.x;
#pragma unroll
    for (int i = 0; i < 32; i++) {
        int idx = tid + i * 256;
        int r = idx >> 8, c = idx & 255;
        s[r][c] = E[(size_t)(row0 + r) * CDIM + c];
    }
    __syncthreads();
    if (tid < 32) {
        float acc = 0.f;
#pragma unroll 8
        for (int c = 0; c < CDIM; c++) {
            float v = s[tid][c];
            acc = __fadd_rn(acc, __fmul_rn(v, v));
        }
        g_esq[stage][row0 + tid] = acc;
    }
}

// ============================================================================
// ||ze||^2, coalesced (stage 0 only; later stages fused into gather).
// ============================================================================
__global__ __launch_bounds__(256) void rownorm_kernel(const float* __restrict__ ze)
{
    __shared__ float s[32][257];
    int row0 = blockIdx.x * 32;
    int tid = threadIdx.x;
#pragma unroll
    for (int i = 0; i < 32; i++) {
        int idx = tid + i * 256;
        int r = idx >> 8, c = idx & 255;
        s[r][c] = ze[(size_t)(row0 + r) * CDIM + c];
    }
    __syncthreads();
    if (tid < 32) {
        float acc = 0.f;
#pragma unroll 8
        for (int c = 0; c < CDIM; c++) {
            float v = s[tid][c];
            acc = __fadd_rn(acc, __fmul_rn(v, v));
        }
        g_ze2[row0 + tid] = acc;
    }
}

// ============================================================================
// Fused score-GEMM + argmin, statically scheduled over 2048 fine units.
// Unit u = (row-block u>>4, code-group u&15); each of 148 CTAs processes a
// CONTIGUOUS unit range (contiguity -> persistent ze tile refilled only at
// row-block boundaries, ~2-3x per CTA). 512 threads, 8x8/thread, BN=256,
// double-buffered cp.async E tiles from pre-transposed g_ET.
// Per unit: d_k = fl( fl( Z - fl(2*s_k) ) + esq_k ), thread-local best,
// warp-shuffle butterfly min-reduce (the 32 code-lanes of a row are one
// warp), lane 0 writes g_bestv16/g_besti16. Tie-break lowest index.
// Dynamic smem: As 256x132 | Bs 2 x 32x264 = 202,752 B.
// ============================================================================
#define ASTRIDE 132
#define BSTRIDE 264
#define VQ_SMEM ((256 * ASTRIDE + 2 * 32 * BSTRIDE) * 4)

__global__ __launch_bounds__(512, 1) void vq_argmin_kernel(
    const float* __restrict__ ze,   // NROWS x CDIM
    int stage)
{
    extern __shared__ __align__(16) float sm[];
    float* As = sm;                         // [256 c][ASTRIDE]  persistent
    float* Bs = sm + 256 * ASTRIDE;         // [2][32 kk][BSTRIDE]

    const int tid = threadIdx.x;
    const int tx = tid & 31;                // code group lane 0..31
    const int ty = tid >> 5;                // warp id = row group 0..15
    const float* __restrict__ esq = g_esq[stage];
    const float* __restrict__ ET = g_ET[stage];

    const int u0 = (blockIdx.x * NUNITS) / (int)gridDim.x;
    const int u1 = ((blockIdx.x + 1) * NUNITS) / (int)gridDim.x;
    const int nch = (u1 - u0) * 8;          // 8 chunks (c0 groups) per unit

    const uint32_t bs_u32 = (uint32_t)__cvta_generic_to_shared(Bs);

    // ---- prefetch chunk 0 of unit u0 ----
    {
        const int code0 = (u0 & 15) * 256;
#pragma unroll
        for (int i = 0; i < 4; i++) {
            int idx = tid + i * 512;        // 0..2047 float4 units
            int kk = idx >> 6, c4 = idx & 63;
            cp_async16(bs_u32 + (uint32_t)(kk * BSTRIDE + c4 * 4) * 4,
                       ET + (size_t)kk * KCODES + code0 + c4 * 4);
        }
        asm volatile("cp.async.commit_group;" ::: "memory");
    }

    int cur_mb = -1;
    float zrow[8];
    unsigned long long acc[8][4];

    for (int t = 0; t < nch; t++) {
        const int u = u0 + (t >> 3);
        const int k = t & 7;
        const int mb = u >> 4;
        const int code0 = (u & 15) * 256;
        const int c0 = k * 32;
        const int m0 = mb * 128;

        asm volatile("cp.async.wait_group 0;" ::: "memory");
        __syncthreads();   // chunk t resident; all done with the other buffer

        if (mb != cur_mb) {
            // refill persistent ze tile for the new row-block
#pragma unroll 8
            for (int i = 0; i < 64; i++) {
                int idx = tid + i * 512;
                int c = idx & 255, mm = idx >> 8;
                As[c * ASTRIDE + mm] = ze[(size_t)(m0 + mm) * CDIM + c];
            }
            cur_mb = mb;
#pragma unroll
            for (int i = 0; i < 8; i++) {
                int row = (i < 4) ? (ty * 4 + i) : (64 + ty * 4 + (i - 4));
                zrow[i] = g_ze2[m0 + row];
            }
            __syncthreads();
        }

        // prefetch chunk t+1 into the other buffer
        if (t + 1 < nch) {
            const int un = u0 + ((t + 1) >> 3);
            const int kn = (t + 1) & 7;
            const int code1 = (un & 15) * 256;
            const int c01 = kn * 32;
            const uint32_t dstb = bs_u32 +
                (uint32_t)(((t + 1) & 1) * 32 * BSTRIDE) * 4;
#pragma unroll
            for (int i = 0; i < 4; i++) {
                int idx = tid + i * 512;
                int kk = idx >> 6, c4 = idx & 63;
                cp_async16(dstb + (uint32_t)(kk * BSTRIDE + c4 * 4) * 4,
                           ET + (size_t)(c01 + kk) * KCODES + code1 + c4 * 4);
            }
            asm volatile("cp.async.commit_group;" ::: "memory");
        }

        if (k == 0) {
#pragma unroll
            for (int i = 0; i < 8; i++)
#pragma unroll
                for (int j = 0; j < 4; j++) acc[i][j] = 0ull;
        }

        const float* Bp = Bs + (t & 1) * (32 * BSTRIDE);
#pragma unroll
        for (int kk = 0; kk < 32; kk++) {
            const float* ar = As + (c0 + kk) * ASTRIDE;
            const float* br = Bp + kk * BSTRIDE;
            float4 a0 = *(const float4*)&ar[ty * 4];          // broadcast
            float4 a1 = *(const float4*)&ar[64 + ty * 4];     // broadcast
            unsigned long long aa[8] = {dup2(a0.x), dup2(a0.y), dup2(a0.z), dup2(a0.w),
                                        dup2(a1.x), dup2(a1.y), dup2(a1.z), dup2(a1.w)};
            ulonglong2 b0 = *(const ulonglong2*)&br[tx * 4];
            ulonglong2 b1 = *(const ulonglong2*)&br[128 + tx * 4];
            unsigned long long bb[4] = {b0.x, b0.y, b1.x, b1.y};
#pragma unroll
            for (int i = 0; i < 8; i++)
#pragma unroll
                for (int j = 0; j < 4; j++)
                    fma2(acc[i][j], aa[i], bb[j]);
        }

        // unit complete: argmin epilogue  d = fl( fl(Z - fl(2*s)) + esq )
        if (k == 7) {
            float bestv[8];
            int   besti[8];
#pragma unroll
            for (int i = 0; i < 8; i++) { bestv[i] = 3.4e38f; besti[i] = 0; }

#pragma unroll
            for (int half = 0; half < 2; half++) {
#pragma unroll
                for (int h = 0; h < 2; h++) {
                    int j2 = half * 2 + h;
                    int col = code0 + half * 128 + tx * 4 + h * 2;
                    float eq0 = esq[col];
                    float eq1 = esq[col + 1];
#pragma unroll
                    for (int i = 0; i < 8; i++) {
                        float2 pv = unpk2(acc[i][j2]);
                        float t0 = __fmul_rn(2.0f, pv.x);
                        float v0 = __fadd_rn(__fadd_rn(zrow[i], -t0), eq0);
                        if (v0 < bestv[i]) { bestv[i] = v0; besti[i] = col; }
                        float t1v = __fmul_rn(2.0f, pv.y);
                        float v1 = __fadd_rn(__fadd_rn(zrow[i], -t1v), eq1);
                        if (v1 < bestv[i]) { bestv[i] = v1; besti[i] = col + 1; }
                    }
                }
            }

            // warp butterfly min-reduce over the 32 code lanes (one warp/row)
#pragma unroll
            for (int i = 0; i < 8; i++) {
                float v = bestv[i];
                int  ix = besti[i];
#pragma unroll
                for (int off = 16; off; off >>= 1) {
                    float ov = __shfl_xor_sync(0xffffffffu, v, off);
                    int   oi = __shfl_xor_sync(0xffffffffu, ix, off);
                    if (ov < v || (ov == v && oi < ix)) { v = ov; ix = oi; }
                }
                if (tx == 0) {
                    int row = (i < 4) ? (ty * 4 + i) : (64 + ty * 4 + (i - 4));
                    g_bestv16[u & 15][m0 + row] = v;
                    g_besti16[u & 15][m0 + row] = ix;
                }
            }
        }
    }
}

// ============================================================================
// Gather: merge 16 code-group argmins (strict < over ascending code ranges ->
// first-occurrence); zq = E[nn]; residual; nn as float; accumulate zq_sum;
// stage 3 forms straight-through decoder input. Stages 0-2 also compute the
// NEXT stage's ||ze_next||^2 with the exact sequential XLA chain.
// ============================================================================
__global__ void gather_kernel(const float* __restrict__ ze,
                              const float* __restrict__ E,
                              float* __restrict__ zq_out,
                              float* __restrict__ ze_next,   // null on stage 3
                              float* __restrict__ nn_f,
                              const float* __restrict__ ze1, // stage 3 only
                              int stage)
{
    __shared__ float buf[CDIM];
    int row = blockIdx.x;
    int c = threadIdx.x;

    float bv = g_bestv16[0][row];
    int   bi = g_besti16[0][row];
#pragma unroll
    for (int h = 1; h < 16; h++) {
        float v = g_bestv16[h][row];
        int  ix = g_besti16[h][row];
        if (v < bv) { bv = v; bi = ix; }
    }
    int idx = bi;

    float q = E[(size_t)idx * CDIM + c];
    size_t o = (size_t)row * CDIM + c;
    zq_out[o] = q;
    if (ze_next) {
        float zn = __fadd_rn(ze[o], -q);
        ze_next[o] = zn;
        buf[c] = zn;
    }
    float s = (stage == 0) ? q : __fadd_rn(g_zqsum[o], q);
    if (stage == 3) {
        float z1 = ze1[o];
        s = __fadd_rn(z1, __fadd_rn(s, -z1));   // ze1 + (zq_sum - ze1)
    }
    g_zqsum[o] = s;
    if (c == 0) nn_f[row] = (float)idx;

    if (ze_next) {
        __syncthreads();
        if (c == 0) {
            float acc = 0.f;
#pragma unroll 8
            for (int i = 0; i < CDIM; i++)
                acc = __fadd_rn(acc, __fmul_rn(buf[i], buf[i]));
            g_ze2[row] = acc;
        }
    }
}

// ============================================================================
// kernel_launch
// Output layout (float32): x_hat [N,768] | ze_1..4 [N,256] | zq_1..4 [N,256]
//                          | nn_1..4 [N]
// ============================================================================
extern "C" void kernel_launch(void* const* d_in, const int* in_sizes, int n_in,
                              void* d_out, int out_size)
{
    const float* x     = (const float*)d_in[0];
    const float* W_enc = (const float*)d_in[1];
    const float* b_enc = (const float*)d_in[2];
    const float* E[4]  = {(const float*)d_in[3], (const float*)d_in[4],
                          (const float*)d_in[5], (const float*)d_in[6]};
    const float* W_dec = (const float*)d_in[7];
    const float* b_dec = (const float*)d_in[8];

    float* out = (float*)d_out;

    const size_t NC      = (size_t)NROWS * CDIM;
    const size_t OFF_ZE  = (size_t)NROWS * INDIM;
    const size_t OFF_ZQ  = OFF_ZE + 4 * NC;
    const size_t OFF_NN  = OFF_ZQ + 4 * NC;

    float* xhat = out;
    const float* ze1 = out + OFF_ZE;

    void* zqsum_ptr = nullptr;
    cudaGetSymbolAddress(&zqsum_ptr, g_zqsum);

    cudaFuncSetAttribute(vq_argmin_kernel,
                         cudaFuncAttributeMaxDynamicSharedMemorySize, VQ_SMEM);

    // codebook preprocessing: norms + transposes (one-time)
    esq4_kernel<<<dim3(KCODES / 32, 4), 256>>>(E[0], E[1], E[2], E[3]);
    transpose4_kernel<<<dim3(KCODES / 32, CDIM / 32, 4), dim3(32, 8)>>>(
        E[0], E[1], E[2], E[3]);

    // encoder: ze_1 = x @ W_enc + b_enc
    sgemm_bias_kernel<<<dim3(CDIM / 128, NROWS / 128), 256>>>(
        x, W_enc, b_enc, out + OFF_ZE, NROWS, INDIM, CDIM);

    // ||ze_1||^2 (later stages' norms are fused into gather)
    rownorm_kernel<<<NROWS / 32, 256>>>(out + OFF_ZE);

    // 4 sequential VQ stages
    for (int s = 0; s < 4; s++) {
        const float* zes = out + OFF_ZE + (size_t)s * NC;
        vq_argmin_kernel<<<VQ_GRID, 512, VQ_SMEM>>>(zes, s);
        float* zenext = (s < 3) ? (out + OFF_ZE + (size_t)(s + 1) * NC) : nullptr;
        gather_kernel<<<NROWS, 256>>>(zes, E[s],
                                      out + OFF_ZQ + (size_t)s * NC,
                                      zenext,
                                      out + OFF_NN + (size_t)s * NROWS,
                                      ze1, s);
    }

    // decoder: x_hat = decoder_input @ W_dec + b_dec
    sgemm_bias_kernel<<<dim3(INDIM / 128, NROWS / 128), 256>>>(
        (const float*)zqsum_ptr, W_dec, b_dec, xhat, NROWS, CDIM, INDIM);
}